// round 13
// baseline (speedup 1.0000x reference)
#include <cuda_runtime.h>
#include <cuda.h>
#include <cstdint>

constexpr int B = 2;
constexpr int D = 160;
constexpr int H = 192;
constexpr int W = 160;
constexpr int HW = H * W;
constexpr int N = D * HW;

// output tile per CTA: 32 x 8 x 8
constexpr int TX = 32, TY = 8, TZ = 8;
constexpr int R = 4;
// halo region: 41 x 17 x 17; pad x to 48 (TMA 16B mult, bank-friendly: 48%32=16)
constexpr int BX = 48, BY = 17, BZ = 17;
constexpr int SLICE = BX * BY;            // 816
constexpr int REGION = BX * BY * BZ;      // 13872 floats = 55488 B

constexpr float SZf = (float)D / (float)(D - 1);
constexpr float SYf = (float)H / (float)(H - 1);
constexpr float SXf = (float)W / (float)(W - 1);

__device__ __forceinline__ float sample_one(const float* __restrict__ tile,
                                            const float* __restrict__ s,
                                            float zc, float yc, float xc,
                                            int ox, int oy, int oz) {
    float z0f = floorf(zc), y0f = floorf(yc), x0f = floorf(xc);
    int z0 = (int)z0f, y0 = (int)y0f, x0 = (int)x0f;
    float wz1 = zc - z0f, wy1 = yc - y0f, wx1 = xc - x0f;
    float wz0 = 1.0f - wz1, wy0 = 1.0f - wy1, wx0 = 1.0f - wx1;

    int rz = z0 - oz, ry = y0 - oy, rx = x0 - ox;

    float v000, v001, v010, v011, v100, v101, v110, v111;

    if (((unsigned)rz <= (unsigned)(BZ - 2)) &
        ((unsigned)ry <= (unsigned)(BY - 2)) &
        ((unsigned)rx <= (unsigned)(BX - 2))) {
        const float* t = tile + rz * SLICE + ry * BX + rx;
        v000 = t[0];
        v001 = t[1];
        v010 = t[BX];
        v011 = t[BX + 1];
        v100 = t[SLICE];
        v101 = t[SLICE + 1];
        v110 = t[SLICE + BX];
        v111 = t[SLICE + BX + 1];
    } else {
        bool z0in = (unsigned)z0 < (unsigned)D;
        bool z1in = (unsigned)(z0 + 1) < (unsigned)D;
        bool y0in = (unsigned)y0 < (unsigned)H;
        bool y1in = (unsigned)(y0 + 1) < (unsigned)H;
        bool x0in = (unsigned)x0 < (unsigned)W;
        bool x1in = (unsigned)(x0 + 1) < (unsigned)W;
        int b00 = z0 * HW + y0 * W + x0;
        int b01 = b00 + W;
        int b10 = b00 + HW;
        int b11 = b10 + W;
        v000 = (z0in & y0in & x0in) ? __ldg(s + b00)     : 0.f;
        v001 = (z0in & y0in & x1in) ? __ldg(s + b00 + 1) : 0.f;
        v010 = (z0in & y1in & x0in) ? __ldg(s + b01)     : 0.f;
        v011 = (z0in & y1in & x1in) ? __ldg(s + b01 + 1) : 0.f;
        v100 = (z1in & y0in & x0in) ? __ldg(s + b10)     : 0.f;
        v101 = (z1in & y0in & x1in) ? __ldg(s + b10 + 1) : 0.f;
        v110 = (z1in & y1in & x0in) ? __ldg(s + b11)     : 0.f;
        v111 = (z1in & y1in & x1in) ? __ldg(s + b11 + 1) : 0.f;
    }

    float c00 = v000 * wx0 + v001 * wx1;
    float c01 = v010 * wx0 + v011 * wx1;
    float c10 = v100 * wx0 + v101 * wx1;
    float c11 = v110 * wx0 + v111 * wx1;
    float c0 = c00 * wy0 + c01 * wy1;
    float c1 = c10 * wy0 + c11 * wy1;
    return c0 * wz0 + c1 * wz1;
}

__global__ __launch_bounds__(512, 4)
void warp3d_tma_kernel(const __grid_constant__ CUtensorMap tmap,
                       const float* __restrict__ src,
                       const float* __restrict__ flow,
                       float* __restrict__ out) {
    extern __shared__ float smem_raw[];
    // TMA destination must be 128B-aligned; dynamic smem only guarantees 16B.
    float* tile = (float*)(((uintptr_t)smem_raw + 127) & ~(uintptr_t)127);
    __shared__ __align__(8) unsigned long long mbar;

    const int bx = blockIdx.x * TX;
    const int by = blockIdx.y * TY;
    const int bzi = blockIdx.z;                     // 0 .. (D/TZ)*B - 1
    const int b  = bzi / (D / TZ);
    const int bz = (bzi - b * (D / TZ)) * TZ;
    const int ox = bx - R, oy = by - R, oz = bz - R;

    const int tx = threadIdx.x, ty = threadIdx.y, tz = threadIdx.z;
    const int tid = tx + ty * 8 + tz * 64;          // block (8,8,8)

    uint32_t smem_u32 = (uint32_t)__cvta_generic_to_shared(tile);
    uint32_t mbar_u32 = (uint32_t)__cvta_generic_to_shared(&mbar);

    if (tid == 0) {
        asm volatile("mbarrier.init.shared.b64 [%0], 1;" :: "r"(mbar_u32));
        asm volatile("fence.proxy.async.shared::cta;" ::: "memory");
    }
    __syncthreads();

    if (tid == 0) {
        asm volatile("mbarrier.arrive.expect_tx.shared.b64 _, [%0], %1;"
                     :: "r"(mbar_u32), "r"((unsigned)(REGION * 4)) : "memory");
        asm volatile(
            "cp.async.bulk.tensor.4d.shared::cta.global.tile.mbarrier::complete_tx::bytes "
            "[%0], [%1, {%2, %3, %4, %5}], [%6];"
            :: "r"(smem_u32), "l"(&tmap),
               "r"(ox), "r"(oy), "r"(oz), "r"(b),
               "r"(mbar_u32) : "memory");
    }

    const int gx0 = bx + tx * 4;                    // this thread: x = gx0..gx0+3
    const int gy = by + ty;
    const int gz = bz + tz;
    const float* fbase = flow + (size_t)b * 3 * N;
    const float* s = src + (size_t)b * N;
    float* obase = out + (size_t)b * N;

    // load flow (float4 x 3) — overlaps the TMA fill; only these 12 floats
    // stay live across the wait (keeps the 32-reg clamp spill-free)
    const int vox = gz * HW + gy * W + gx0;
    float4 fz = *(const float4*)(fbase + vox);
    float4 fy = *(const float4*)(fbase + vox + N);
    float4 fx = *(const float4*)(fbase + vox + 2 * N);

    // wait for TMA (phase parity 0)
    asm volatile(
        "{\n\t.reg .pred P;\n\t"
        "W%=:\n\t"
        "mbarrier.try_wait.parity.acquire.cta.shared::cta.b64 P, [%0], 0, 0x989680;\n\t"
        "@!P bra W%=;\n\t}"
        :: "r"(mbar_u32) : "memory");

    // coords + samples after the wait (small live set before it)
    const float cz = fmaf((float)gz, SZf, -0.5f);
    const float cy = fmaf((float)gy, SYf, -0.5f);

    float fzv[4] = {fz.x, fz.y, fz.z, fz.w};
    float fyv[4] = {fy.x, fy.y, fy.z, fy.w};
    float fxv[4] = {fx.x, fx.y, fx.z, fx.w};

    float4 o;
    float ov[4];
#pragma unroll
    for (int k = 0; k < 4; ++k) {
        float zc = fmaf(fzv[k], SZf, cz);
        float yc = fmaf(fyv[k], SYf, cy);
        float xc = fmaf((float)(gx0 + k) + fxv[k], SXf, -0.5f);
        ov[k] = sample_one(tile, s, zc, yc, xc, ox, oy, oz);
    }
    o.x = ov[0]; o.y = ov[1]; o.z = ov[2]; o.w = ov[3];

    *(float4*)(obase + vox) = o;
}

extern "C" void kernel_launch(void* const* d_in, const int* in_sizes, int n_in,
                              void* d_out, int out_size) {
    const float* src = (const float*)d_in[0];
    const float* flow = (const float*)d_in[1];
    float* out = (float*)d_out;

    // Fetch driver-API tensor map encoder through the runtime (no -lcuda needed).
    typedef CUresult (*EncodeFn)(
        CUtensorMap*, CUtensorMapDataType, cuuint32_t, void*,
        const cuuint64_t*, const cuuint64_t*, const cuuint32_t*, const cuuint32_t*,
        CUtensorMapInterleave, CUtensorMapSwizzle, CUtensorMapL2promotion,
        CUtensorMapFloatOOBfill);
    void* fp = nullptr;
    cudaDriverEntryPointQueryResult qres;
    cudaGetDriverEntryPointByVersion("cuTensorMapEncodeTiled", &fp, 12000,
                                     cudaEnableDefault, &qres);
    EncodeFn encode = (EncodeFn)fp;

    CUtensorMap tmap;
    cuuint64_t dims[4]    = {(cuuint64_t)W, (cuuint64_t)H, (cuuint64_t)D, (cuuint64_t)B};
    cuuint64_t strides[3] = {(cuuint64_t)W * 4, (cuuint64_t)HW * 4, (cuuint64_t)N * 4};
    cuuint32_t box[4]     = {BX, BY, BZ, 1};
    cuuint32_t estr[4]    = {1, 1, 1, 1};
    encode(&tmap, CU_TENSOR_MAP_DATA_TYPE_FLOAT32, 4, (void*)src,
           dims, strides, box, estr,
           CU_TENSOR_MAP_INTERLEAVE_NONE, CU_TENSOR_MAP_SWIZZLE_NONE,
           CU_TENSOR_MAP_L2_PROMOTION_L2_128B, CU_TENSOR_MAP_FLOAT_OOB_FILL_NONE);

    const int smem_bytes = REGION * 4 + 128;   // +128 for manual alignment
    cudaFuncSetAttribute(warp3d_tma_kernel,
                         cudaFuncAttributeMaxDynamicSharedMemorySize, smem_bytes);

    dim3 block(8, 8, 8);
    dim3 grid(W / TX, H / TY, (D / TZ) * B);   // 5 x 24 x 40
    warp3d_tma_kernel<<<grid, block, smem_bytes>>>(tmap, src, flow, out);
}

// round 14
// speedup vs baseline: 1.0825x; 1.0825x over previous
#include <cuda_runtime.h>
#include <cuda.h>
#include <cstdint>

constexpr int B = 2;
constexpr int D = 160;
constexpr int H = 192;
constexpr int W = 160;
constexpr int HW = H * W;
constexpr int N = D * HW;

// output tile per CTA: 32 x 8 x 8 (R11 winner shape)
constexpr int TX = 32, TY = 8, TZ = 8;
constexpr int R = 4;
// halo region: 41 x 17 x 17; pad x to 48 (TMA 16B mult, bank-friendly: 48%32=16)
constexpr int BX = 48, BY = 17, BZ = 17;
constexpr int SLICE = BX * BY;            // 816
constexpr int REGION = BX * BY * BZ;      // 13872 floats = 55488 B
// two-slab fill: A = z slices [0,13] (14), B = [14,16] (3)
constexpr int AZ = 14, BZ2 = 3;
constexpr unsigned ABYTES = BX * BY * AZ * 4;   // 45696
constexpr unsigned BBYTES = BX * BY * BZ2 * 4;  //  9792

constexpr float SZf = (float)D / (float)(D - 1);
constexpr float SYf = (float)H / (float)(H - 1);
constexpr float SXf = (float)W / (float)(W - 1);

__device__ __forceinline__ float sample_one(const float* __restrict__ tile,
                                            const float* __restrict__ s,
                                            float zc, float yc, float xc,
                                            int ox, int oy, int oz, int rzmax) {
    float z0f = floorf(zc), y0f = floorf(yc), x0f = floorf(xc);
    int z0 = (int)z0f, y0 = (int)y0f, x0 = (int)x0f;
    float wz1 = zc - z0f, wy1 = yc - y0f, wx1 = xc - x0f;
    float wz0 = 1.0f - wz1, wy0 = 1.0f - wy1, wx0 = 1.0f - wx1;

    int rz = z0 - oz, ry = y0 - oy, rx = x0 - ox;

    float v000, v001, v010, v011, v100, v101, v110, v111;

    if (((unsigned)rz <= (unsigned)rzmax) &
        ((unsigned)ry <= (unsigned)(BY - 2)) &
        ((unsigned)rx <= (unsigned)(BX - 2))) {
        const float* t = tile + rz * SLICE + ry * BX + rx;
        v000 = t[0];
        v001 = t[1];
        v010 = t[BX];
        v011 = t[BX + 1];
        v100 = t[SLICE];
        v101 = t[SLICE + 1];
        v110 = t[SLICE + BX];
        v111 = t[SLICE + BX + 1];
    } else {
        bool z0in = (unsigned)z0 < (unsigned)D;
        bool z1in = (unsigned)(z0 + 1) < (unsigned)D;
        bool y0in = (unsigned)y0 < (unsigned)H;
        bool y1in = (unsigned)(y0 + 1) < (unsigned)H;
        bool x0in = (unsigned)x0 < (unsigned)W;
        bool x1in = (unsigned)(x0 + 1) < (unsigned)W;
        int b00 = z0 * HW + y0 * W + x0;
        int b01 = b00 + W;
        int b10 = b00 + HW;
        int b11 = b10 + W;
        v000 = (z0in & y0in & x0in) ? __ldg(s + b00)     : 0.f;
        v001 = (z0in & y0in & x1in) ? __ldg(s + b00 + 1) : 0.f;
        v010 = (z0in & y1in & x0in) ? __ldg(s + b01)     : 0.f;
        v011 = (z0in & y1in & x1in) ? __ldg(s + b01 + 1) : 0.f;
        v100 = (z1in & y0in & x0in) ? __ldg(s + b10)     : 0.f;
        v101 = (z1in & y0in & x1in) ? __ldg(s + b10 + 1) : 0.f;
        v110 = (z1in & y1in & x0in) ? __ldg(s + b11)     : 0.f;
        v111 = (z1in & y1in & x1in) ? __ldg(s + b11 + 1) : 0.f;
    }

    float c00 = v000 * wx0 + v001 * wx1;
    float c01 = v010 * wx0 + v011 * wx1;
    float c10 = v100 * wx0 + v101 * wx1;
    float c11 = v110 * wx0 + v111 * wx1;
    float c0 = c00 * wy0 + c01 * wy1;
    float c1 = c10 * wy0 + c11 * wy1;
    return c0 * wz0 + c1 * wz1;
}

__device__ __forceinline__ void mbar_wait0(uint32_t mbar_u32) {
    asm volatile(
        "{\n\t.reg .pred P;\n\t"
        "W%=:\n\t"
        "mbarrier.try_wait.parity.acquire.cta.shared::cta.b64 P, [%0], 0, 0x989680;\n\t"
        "@!P bra W%=;\n\t}"
        :: "r"(mbar_u32) : "memory");
}

__global__ __launch_bounds__(512, 4)
void warp3d_tma_kernel(const __grid_constant__ CUtensorMap tmapA,
                       const __grid_constant__ CUtensorMap tmapB,
                       const float* __restrict__ src,
                       const float* __restrict__ flow,
                       float* __restrict__ out) {
    extern __shared__ float smem_raw[];
    // TMA destination must be 128B-aligned; dynamic smem only guarantees 16B.
    float* tile = (float*)(((uintptr_t)smem_raw + 127) & ~(uintptr_t)127);
    __shared__ __align__(8) unsigned long long mbarA, mbarB;

    const int bx = blockIdx.x * TX;
    const int by = blockIdx.y * TY;
    const int bzi = blockIdx.z;                     // 0 .. (D/TZ)*B - 1
    const int b  = bzi / (D / TZ);
    const int bz = (bzi - b * (D / TZ)) * TZ;
    const int ox = bx - R, oy = by - R, oz = bz - R;

    const int tx = threadIdx.x, ty = threadIdx.y, tz = threadIdx.z;
    const int tid = tx + ty * 16 + tz * 128;        // block (16,8,4)

    uint32_t smem_u32 = (uint32_t)__cvta_generic_to_shared(tile);
    uint32_t mbarA_u32 = (uint32_t)__cvta_generic_to_shared(&mbarA);
    uint32_t mbarB_u32 = (uint32_t)__cvta_generic_to_shared(&mbarB);

    if (tid == 0) {
        asm volatile("mbarrier.init.shared.b64 [%0], 1;" :: "r"(mbarA_u32));
        asm volatile("mbarrier.init.shared.b64 [%0], 1;" :: "r"(mbarB_u32));
        asm volatile("fence.proxy.async.shared::cta;" ::: "memory");
    }
    __syncthreads();

    if (tid == 0) {
        // slab A: z slices [0, AZ)
        asm volatile("mbarrier.arrive.expect_tx.shared.b64 _, [%0], %1;"
                     :: "r"(mbarA_u32), "r"(ABYTES) : "memory");
        asm volatile(
            "cp.async.bulk.tensor.4d.shared::cta.global.tile.mbarrier::complete_tx::bytes "
            "[%0], [%1, {%2, %3, %4, %5}], [%6];"
            :: "r"(smem_u32), "l"(&tmapA),
               "r"(ox), "r"(oy), "r"(oz), "r"(b),
               "r"(mbarA_u32) : "memory");
        // slab B: z slices [AZ, BZ)
        asm volatile("mbarrier.arrive.expect_tx.shared.b64 _, [%0], %1;"
                     :: "r"(mbarB_u32), "r"(BBYTES) : "memory");
        asm volatile(
            "cp.async.bulk.tensor.4d.shared::cta.global.tile.mbarrier::complete_tx::bytes "
            "[%0], [%1, {%2, %3, %4, %5}], [%6];"
            :: "r"(smem_u32 + (unsigned)(AZ * SLICE * 4)), "l"(&tmapB),
               "r"(ox), "r"(oy), "r"(oz + AZ), "r"(b),
               "r"(mbarB_u32) : "memory");
    }

    const int gx0 = bx + tx * 2;                    // this thread: x = gx0, gx0+1
    const int gy = by + ty;
    const float* fbase = flow + (size_t)b * 3 * N;
    const float* s = src + (size_t)b * N;
    float* obase = out + (size_t)b * N;

    // prefetch first iteration's flow (float2: 2 voxels) while TMA is in flight
    int vox0 = (bz + tz) * HW + gy * W + gx0;
    float2 pfz = *(const float2*)(fbase + vox0);
    float2 pfy = *(const float2*)(fbase + vox0 + N);
    float2 pfx = *(const float2*)(fbase + vox0 + 2 * N);

    // wait for slab A only (iter 0's fast path reads rz+1 <= 13)
    mbar_wait0(mbarA_u32);

#pragma unroll
    for (int i = 0; i < 2; ++i) {
        const int lz = i * 4 + tz;            // 0..7
        const int gz = bz + lz;
        const int vox = gz * HW + gy * W + gx0;

        float2 fz = pfz, fy = pfy, fx = pfx;
        if (i == 0) {                          // prefetch next iteration
            int nvox = vox + 4 * HW;
            pfz = *(const float2*)(fbase + nvox);
            pfy = *(const float2*)(fbase + nvox + N);
            pfx = *(const float2*)(fbase + nvox + 2 * N);
        }

        // iter0 fast path limited to slab A (rz <= AZ-2); iter1 full region
        const int rzmax = (i == 0) ? (AZ - 2) : (BZ - 2);

        float zc0 = fmaf((float)gz + fz.x, SZf, -0.5f);
        float yc0 = fmaf((float)gy + fy.x, SYf, -0.5f);
        float xc0 = fmaf((float)gx0 + fx.x, SXf, -0.5f);

        float zc1 = fmaf((float)gz + fz.y, SZf, -0.5f);
        float yc1 = fmaf((float)gy + fy.y, SYf, -0.5f);
        float xc1 = fmaf((float)(gx0 + 1) + fx.y, SXf, -0.5f);

        float2 o;
        o.x = sample_one(tile, s, zc0, yc0, xc0, ox, oy, oz, rzmax);
        o.y = sample_one(tile, s, zc1, yc1, xc1, ox, oy, oz, rzmax);

        *(float2*)(obase + vox) = o;

        if (i == 0) mbar_wait0(mbarB_u32);     // slab B ready before iter 1
    }
}

extern "C" void kernel_launch(void* const* d_in, const int* in_sizes, int n_in,
                              void* d_out, int out_size) {
    const float* src = (const float*)d_in[0];
    const float* flow = (const float*)d_in[1];
    float* out = (float*)d_out;

    // Fetch driver-API tensor map encoder through the runtime (no -lcuda needed).
    typedef CUresult (*EncodeFn)(
        CUtensorMap*, CUtensorMapDataType, cuuint32_t, void*,
        const cuuint64_t*, const cuuint64_t*, const cuuint32_t*, const cuuint32_t*,
        CUtensorMapInterleave, CUtensorMapSwizzle, CUtensorMapL2promotion,
        CUtensorMapFloatOOBfill);
    void* fp = nullptr;
    cudaDriverEntryPointQueryResult qres;
    cudaGetDriverEntryPointByVersion("cuTensorMapEncodeTiled", &fp, 12000,
                                     cudaEnableDefault, &qres);
    EncodeFn encode = (EncodeFn)fp;

    cuuint64_t dims[4]    = {(cuuint64_t)W, (cuuint64_t)H, (cuuint64_t)D, (cuuint64_t)B};
    cuuint64_t strides[3] = {(cuuint64_t)W * 4, (cuuint64_t)HW * 4, (cuuint64_t)N * 4};
    cuuint32_t estr[4]    = {1, 1, 1, 1};

    CUtensorMap tmapA, tmapB;
    cuuint32_t boxA[4] = {BX, BY, AZ, 1};
    encode(&tmapA, CU_TENSOR_MAP_DATA_TYPE_FLOAT32, 4, (void*)src,
           dims, strides, boxA, estr,
           CU_TENSOR_MAP_INTERLEAVE_NONE, CU_TENSOR_MAP_SWIZZLE_NONE,
           CU_TENSOR_MAP_L2_PROMOTION_L2_128B, CU_TENSOR_MAP_FLOAT_OOB_FILL_NONE);
    cuuint32_t boxB[4] = {BX, BY, BZ2, 1};
    encode(&tmapB, CU_TENSOR_MAP_DATA_TYPE_FLOAT32, 4, (void*)src,
           dims, strides, boxB, estr,
           CU_TENSOR_MAP_INTERLEAVE_NONE, CU_TENSOR_MAP_SWIZZLE_NONE,
           CU_TENSOR_MAP_L2_PROMOTION_L2_128B, CU_TENSOR_MAP_FLOAT_OOB_FILL_NONE);

    const int smem_bytes = REGION * 4 + 128;   // +128 for manual alignment
    cudaFuncSetAttribute(warp3d_tma_kernel,
                         cudaFuncAttributeMaxDynamicSharedMemorySize, smem_bytes);

    dim3 block(16, 8, 4);
    dim3 grid(W / TX, H / TY, (D / TZ) * B);   // 5 x 24 x 40
    warp3d_tma_kernel<<<grid, block, smem_bytes>>>(tmapA, tmapB, src, flow, out);
}